// round 1
// baseline (speedup 1.0000x reference)
#include <cuda_runtime.h>
#include <cstdint>

// Problem constants
#define E_TOT 43234
#define D_HALF 256          // complex dimension
#define DP 128              // d-pairs (f32x2 packing over d)
#define NBLK 296            // 2 CTAs/SM * 148 SMs
#define NTHR 256
#define TOTAL_WARPS (NBLK * (NTHR / 32))

// Rotated (and NEGATED) head, transposed: g_head[dpair*32 + b] = {-re(2dp), -re(2dp+1), -im(2dp), -im(2dp+1)}
__device__ float4 g_head[DP * 32];

// ---------- f32x2 packed helpers (sm_103a) ----------
__device__ __forceinline__ unsigned long long pack2(float lo, float hi) {
    unsigned long long r;
    asm("mov.b64 %0, {%1, %2};" : "=l"(r) : "f"(lo), "f"(hi));
    return r;
}
__device__ __forceinline__ void unpack2(unsigned long long v, float& lo, float& hi) {
    asm("mov.b64 {%0, %1}, %2;" : "=f"(lo), "=f"(hi) : "l"(v));
}
__device__ __forceinline__ unsigned long long addx2(unsigned long long a, unsigned long long b) {
    unsigned long long r;
    asm("add.rn.f32x2 %0, %1, %2;" : "=l"(r) : "l"(a), "l"(b));
    return r;
}
__device__ __forceinline__ unsigned long long mulx2(unsigned long long a, unsigned long long b) {
    unsigned long long r;
    asm("mul.rn.f32x2 %0, %1, %2;" : "=l"(r) : "l"(a), "l"(b));
    return r;
}
__device__ __forceinline__ unsigned long long fmax2(unsigned long long a, unsigned long long b, unsigned long long c) {
    unsigned long long r;
    asm("fma.rn.f32x2 %0, %1, %2, %3;" : "=l"(r) : "l"(a), "l"(b), "l"(c));
    return r;
}
__device__ __forceinline__ float sqrt_approx(float x) {
    float r;
    asm("sqrt.approx.f32 %0, %1;" : "=f"(r) : "f"(x));
    return r;
}

// ---------- prep: rotate head by relation phase, negate + transpose ----------
// grid (32), block (256); b = blockIdx.x, d = threadIdx.x
__global__ void prep_kernel(const float* __restrict__ head, const float* __restrict__ rel) {
    int b = blockIdx.x;
    int d = threadIdx.x;
    float re_h = head[b * 2 * D_HALF + d];
    float im_h = head[b * 2 * D_HALF + D_HALF + d];
    // phase = rel / (REL_RANGE/pi) = rel * 32*pi
    float phase = rel[b * D_HALF + d] * 100.53096491487338f;
    float s, c;
    sincosf(phase, &s, &c);
    float re_rot = re_h * c - im_h * s;
    float im_rot = re_h * s + im_h * c;
    int dp = d >> 1, k = d & 1;
    float* base = reinterpret_cast<float*>(&g_head[dp * 32 + b]);
    base[k]     = -re_rot;  // negated: sub becomes add.f32x2, sign vanishes in square
    base[2 + k] = -im_rot;
}

// ---------- main: warp = entity, lane = b ----------
__global__ void __launch_bounds__(NTHR, 2)
dist_kernel(const float* __restrict__ ent, float* __restrict__ out) {
    extern __shared__ float4 sh[];  // 128*32 float4 = 64KB
    for (int i = threadIdx.x; i < DP * 32; i += NTHR) sh[i] = g_head[i];
    __syncthreads();

    const int gw   = (blockIdx.x * NTHR + threadIdx.x) >> 5;
    const int lane = threadIdx.x & 31;

    for (int e = gw; e < E_TOT; e += TOTAL_WARPS) {
        const float4* __restrict__ rep = reinterpret_cast<const float4*>(ent + (size_t)e * 2 * D_HALF);
        const float4* __restrict__ imp = reinterpret_cast<const float4*>(ent + (size_t)e * 2 * D_HALF + D_HALF);
        float acc0 = 0.0f, acc1 = 0.0f;

#pragma unroll 4
        for (int q = 0; q < D_HALF / 4; q++) {
            float4 tre = __ldg(rep + q);                 // re[4q..4q+3], warp-uniform broadcast
            float4 tim = __ldg(imp + q);                 // im[4q..4q+3]
            float4 h0 = sh[(2 * q) * 32 + lane];         // {-re,-re,-im,-im} for pair 2q
            float4 h1 = sh[(2 * q + 1) * 32 + lane];     // pair 2q+1

            // pair 0: d = 4q, 4q+1
            unsigned long long a = addx2(pack2(tre.x, tre.y), pack2(h0.x, h0.y));  // t - rot (re)
            unsigned long long b = addx2(pack2(tim.x, tim.y), pack2(h0.z, h0.w));  // t - rot (im)
            unsigned long long p = fmax2(b, b, mulx2(a, a));
            float p0, p1;
            unpack2(p, p0, p1);
            acc0 += sqrt_approx(p0);
            acc1 += sqrt_approx(p1);

            // pair 1: d = 4q+2, 4q+3
            a = addx2(pack2(tre.z, tre.w), pack2(h1.x, h1.y));
            b = addx2(pack2(tim.z, tim.w), pack2(h1.z, h1.w));
            p = fmax2(b, b, mulx2(a, a));
            unpack2(p, p0, p1);
            acc0 += sqrt_approx(p0);
            acc1 += sqrt_approx(p1);
        }

        out[(size_t)lane * E_TOT + e] = 6.0f - (acc0 + acc1);
    }
}

extern "C" void kernel_launch(void* const* d_in, const int* in_sizes, int n_in,
                              void* d_out, int out_size) {
    const float* head = (const float*)d_in[0];   // (32, 512)
    const float* rel  = (const float*)d_in[1];   // (32, 256)
    const float* ent  = (const float*)d_in[2];   // (43234, 512)
    float* out = (float*)d_out;                  // (32, 43234)

    cudaFuncSetAttribute(dist_kernel, cudaFuncAttributeMaxDynamicSharedMemorySize, 65536);

    prep_kernel<<<32, 256>>>(head, rel);
    dist_kernel<<<NBLK, NTHR, 65536>>>(ent, out);
}

// round 2
// speedup vs baseline: 1.3566x; 1.3566x over previous
#include <cuda_runtime.h>
#include <cstdint>

#define E_TOT 43234
#define D_HALF 256
#define DP 128              // d-pairs
#define NBLK 296            // 2 CTA/SM * 148 SM
#define NTHR 256
#define ET 4                // entities register-tiled per warp
#define TOTAL_WARPS (NBLK * (NTHR / 32))

// Rotated (NEGATED) head, transposed: g_head[dp*32 + b] = {-re(2dp), -re(2dp+1), -im(2dp), -im(2dp+1)}
// Viewed as ulonglong2: .x = packed re pair, .y = packed im pair  (f32x2 operand-ready)
__device__ float4 g_head[DP * 32];

// ---------- f32x2 packed helpers (sm_103a) ----------
__device__ __forceinline__ unsigned long long addx2(unsigned long long a, unsigned long long b) {
    unsigned long long r;
    asm("add.rn.f32x2 %0, %1, %2;" : "=l"(r) : "l"(a), "l"(b));
    return r;
}
__device__ __forceinline__ unsigned long long mulx2(unsigned long long a, unsigned long long b) {
    unsigned long long r;
    asm("mul.rn.f32x2 %0, %1, %2;" : "=l"(r) : "l"(a), "l"(b));
    return r;
}
__device__ __forceinline__ unsigned long long fmax2(unsigned long long a, unsigned long long b, unsigned long long c) {
    unsigned long long r;
    asm("fma.rn.f32x2 %0, %1, %2, %3;" : "=l"(r) : "l"(a), "l"(b), "l"(c));
    return r;
}
__device__ __forceinline__ void unpack2(unsigned long long v, float& lo, float& hi) {
    asm("mov.b64 {%0, %1}, %2;" : "=f"(lo), "=f"(hi) : "l"(v));
}
__device__ __forceinline__ float sqrt_approx(float x) {
    float r;
    asm("sqrt.approx.f32 %0, %1;" : "=f"(r) : "f"(x));
    return r;
}

// ---------- prep: rotate head, negate + transpose ----------
__global__ void prep_kernel(const float* __restrict__ head, const float* __restrict__ rel) {
    int b = blockIdx.x;
    int d = threadIdx.x;
    float re_h = head[b * 2 * D_HALF + d];
    float im_h = head[b * 2 * D_HALF + D_HALF + d];
    float phase = rel[b * D_HALF + d] * 100.53096491487338f;  // rel * 32*pi
    float s, c;
    sincosf(phase, &s, &c);
    float re_rot = re_h * c - im_h * s;
    float im_rot = re_h * s + im_h * c;
    int dp = d >> 1, k = d & 1;
    float* base = reinterpret_cast<float*>(&g_head[dp * 32 + b]);
    base[k]     = -re_rot;
    base[2 + k] = -im_rot;
}

// ---------- main: warp = 4-entity tile, lane = b ----------
__global__ void __launch_bounds__(NTHR, 2)
dist_kernel(const float* __restrict__ ent, float* __restrict__ out) {
    extern __shared__ ulonglong2 sh2[];  // [DP*32] = 64KB; sh2[dp*32+lane] = {re_pair, im_pair}
    {
        const float4* src = g_head;
        float4* dst = reinterpret_cast<float4*>(sh2);
        for (int i = threadIdx.x; i < DP * 32; i += NTHR) dst[i] = src[i];
    }
    __syncthreads();

    const int gw   = (blockIdx.x * NTHR + threadIdx.x) >> 5;
    const int lane = threadIdx.x & 31;

    for (int e = gw * ET; e < E_TOT; e += TOTAL_WARPS * ET) {
        // entity row pointers as ulonglong2 (16B chunks); clamp tail rows (store is guarded)
        const ulonglong2* __restrict__ row[ET];
#pragma unroll
        for (int t = 0; t < ET; t++) {
            int ec = (e + t < E_TOT) ? (e + t) : (E_TOT - 1);
            row[t] = reinterpret_cast<const ulonglong2*>(ent + (size_t)ec * 2 * D_HALF);
        }

        float acc0[ET], acc1[ET];
#pragma unroll
        for (int t = 0; t < ET; t++) { acc0[t] = 0.0f; acc1[t] = 0.0f; }

#pragma unroll 2
        for (int q = 0; q < D_HALF / 4; q++) {
            // head pairs for d = {4q,4q+1} and {4q+2,4q+3}: one LDS.128 each, amortized over ET entities
            ulonglong2 h0 = sh2[(2 * q) * 32 + lane];
            ulonglong2 h1 = sh2[(2 * q + 1) * 32 + lane];

#pragma unroll
            for (int t = 0; t < ET; t++) {
                ulonglong2 tre = __ldg(row[t] + q);            // re floats d=4q..4q+3
                ulonglong2 tim = __ldg(row[t] + 64 + q);       // im floats d=4q..4q+3

                unsigned long long a0 = addx2(tre.x, h0.x);    // (t_re - rot_re), pair {4q,4q+1}
                unsigned long long b0 = addx2(tim.x, h0.y);
                unsigned long long a1 = addx2(tre.y, h1.x);    // pair {4q+2,4q+3}
                unsigned long long b1 = addx2(tim.y, h1.y);

                unsigned long long p0 = fmax2(b0, b0, mulx2(a0, a0));
                unsigned long long p1 = fmax2(b1, b1, mulx2(a1, a1));

                float x0, x1, y0, y1;
                unpack2(p0, x0, x1);
                unpack2(p1, y0, y1);
                acc0[t] += sqrt_approx(x0);
                acc1[t] += sqrt_approx(x1);
                acc0[t] += sqrt_approx(y0);
                acc1[t] += sqrt_approx(y1);
            }
        }

#pragma unroll
        for (int t = 0; t < ET; t++) {
            if (e + t < E_TOT)
                out[(size_t)lane * E_TOT + (e + t)] = 6.0f - (acc0[t] + acc1[t]);
        }
    }
}

extern "C" void kernel_launch(void* const* d_in, const int* in_sizes, int n_in,
                              void* d_out, int out_size) {
    const float* head = (const float*)d_in[0];   // (32, 512)
    const float* rel  = (const float*)d_in[1];   // (32, 256)
    const float* ent  = (const float*)d_in[2];   // (43234, 512)
    float* out = (float*)d_out;                  // (32, 43234)

    cudaFuncSetAttribute(dist_kernel, cudaFuncAttributeMaxDynamicSharedMemorySize, 65536);

    prep_kernel<<<32, 256>>>(head, rel);
    dist_kernel<<<NBLK, NTHR, 65536>>>(ent, out);
}

// round 3
// speedup vs baseline: 1.4278x; 1.0525x over previous
#include <cuda_runtime.h>
#include <cstdint>

#define E_TOT 43234
#define D_HALF 256
#define DP 128              // d-pairs
#define NBLK 296            // 2 CTA/SM * 148 SM
#define NTHR 256
#define ET 4                // entities register-tiled per warp
#define TOTAL_WARPS (NBLK * (NTHR / 32))

// Rotated (NEGATED) head, transposed: g_head[dp*32 + b] = {-re(2dp), -re(2dp+1), -im(2dp), -im(2dp+1)}
// As ulonglong2: .x = packed re pair, .y = packed im pair (f32x2 operand-ready)
__device__ float4 g_head[DP * 32];

// ---------- f32x2 packed helpers (sm_103a) ----------
__device__ __forceinline__ unsigned long long addx2(unsigned long long a, unsigned long long b) {
    unsigned long long r;
    asm("add.rn.f32x2 %0, %1, %2;" : "=l"(r) : "l"(a), "l"(b));
    return r;
}
__device__ __forceinline__ unsigned long long mulx2(unsigned long long a, unsigned long long b) {
    unsigned long long r;
    asm("mul.rn.f32x2 %0, %1, %2;" : "=l"(r) : "l"(a), "l"(b));
    return r;
}
__device__ __forceinline__ unsigned long long fmax2(unsigned long long a, unsigned long long b, unsigned long long c) {
    unsigned long long r;
    asm("fma.rn.f32x2 %0, %1, %2, %3;" : "=l"(r) : "l"(a), "l"(b), "l"(c));
    return r;
}
__device__ __forceinline__ void unpack2(unsigned long long v, float& lo, float& hi) {
    asm("mov.b64 {%0, %1}, %2;" : "=f"(lo), "=f"(hi) : "l"(v));
}
__device__ __forceinline__ float sqrt_approx(float x) {
    float r;
    asm("sqrt.approx.f32 %0, %1;" : "=f"(r) : "f"(x));
    return r;
}

// ---------- prep: rotate head, negate + transpose ----------
__global__ void prep_kernel(const float* __restrict__ head, const float* __restrict__ rel) {
    int b = blockIdx.x;
    int d = threadIdx.x;
    float re_h = head[b * 2 * D_HALF + d];
    float im_h = head[b * 2 * D_HALF + D_HALF + d];
    float phase = rel[b * D_HALF + d] * 100.53096491487338f;  // rel * 32*pi
    float s, c;
    sincosf(phase, &s, &c);
    float re_rot = re_h * c - im_h * s;
    float im_rot = re_h * s + im_h * c;
    int dp = d >> 1, k = d & 1;
    float* base = reinterpret_cast<float*>(&g_head[dp * 32 + b]);
    base[k]     = -re_rot;
    base[2 + k] = -im_rot;
}

// ---------- main: warp = 4-entity tile, lane = b; software-pipelined q loop ----------
__global__ void __launch_bounds__(NTHR, 2)
dist_kernel(const float* __restrict__ ent, float* __restrict__ out) {
    extern __shared__ ulonglong2 sh2[];  // [DP*32] = 64KB; sh2[dp*32+lane] = {re_pair, im_pair}
    {
        const float4* src = g_head;
        float4* dst = reinterpret_cast<float4*>(sh2);
        for (int i = threadIdx.x; i < DP * 32; i += NTHR) dst[i] = src[i];
    }
    __syncthreads();

    const int gw   = (blockIdx.x * NTHR + threadIdx.x) >> 5;
    const int lane = threadIdx.x & 31;
    const ulonglong2* __restrict__ hs = sh2 + lane;  // hs[(2q)*32], hs[(2q+1)*32]

    for (int e = gw * ET; e < E_TOT; e += TOTAL_WARPS * ET) {
        // branch-free tail: clamp the whole 4-entity window (overlap writes identical values)
        const int e0 = (e <= E_TOT - ET) ? e : (E_TOT - ET);
        const ulonglong2* __restrict__ base =
            reinterpret_cast<const ulonglong2*>(ent) + (size_t)e0 * (2 * D_HALF / 4);
        // per-entity offsets (in ulonglong2): t*128 + q (re), t*128 + 64 + q (im)

        float acc0[ET], acc1[ET];
#pragma unroll
        for (int t = 0; t < ET; t++) { acc0[t] = 0.0f; acc1[t] = 0.0f; }

        ulonglong2 cre[ET], cim[ET], nre[ET], nim[ET];
        ulonglong2 ch0, ch1, nh0, nh1;

        // prologue: q = 0
        ch0 = hs[0];
        ch1 = hs[32];
#pragma unroll
        for (int t = 0; t < ET; t++) {
            cre[t] = __ldg(base + t * 128);
            cim[t] = __ldg(base + t * 128 + 64);
        }

#pragma unroll 2
        for (int q = 0; q < D_HALF / 4; q++) {
            // prefetch q+1 (clamped to 0 on last iter: in-bounds, discarded)
            const int qn = (q + 1 < D_HALF / 4) ? (q + 1) : 0;
            nh0 = hs[(2 * qn) * 32];
            nh1 = hs[(2 * qn) * 32 + 32];
#pragma unroll
            for (int t = 0; t < ET; t++) {
                nre[t] = __ldg(base + t * 128 + qn);
                nim[t] = __ldg(base + t * 128 + 64 + qn);
            }

            // compute on current
#pragma unroll
            for (int t = 0; t < ET; t++) {
                unsigned long long a0 = addx2(cre[t].x, ch0.x);
                unsigned long long b0 = addx2(cim[t].x, ch0.y);
                unsigned long long a1 = addx2(cre[t].y, ch1.x);
                unsigned long long b1 = addx2(cim[t].y, ch1.y);
                unsigned long long p0 = fmax2(b0, b0, mulx2(a0, a0));
                unsigned long long p1 = fmax2(b1, b1, mulx2(a1, a1));
                float x0, x1, y0, y1;
                unpack2(p0, x0, x1);
                unpack2(p1, y0, y1);
                acc0[t] += sqrt_approx(x0) + sqrt_approx(y0);
                acc1[t] += sqrt_approx(x1) + sqrt_approx(y1);
            }

            // rotate buffers (renamed away by unroll 2)
            ch0 = nh0;
            ch1 = nh1;
#pragma unroll
            for (int t = 0; t < ET; t++) { cre[t] = nre[t]; cim[t] = nim[t]; }
        }

        // two 8B stores (E_TOT even, e0 even -> 8B aligned)
        float2* op = reinterpret_cast<float2*>(out + (size_t)lane * E_TOT + e0);
        op[0] = make_float2(6.0f - (acc0[0] + acc1[0]), 6.0f - (acc0[1] + acc1[1]));
        op[1] = make_float2(6.0f - (acc0[2] + acc1[2]), 6.0f - (acc0[3] + acc1[3]));
    }
}

extern "C" void kernel_launch(void* const* d_in, const int* in_sizes, int n_in,
                              void* d_out, int out_size) {
    const float* head = (const float*)d_in[0];   // (32, 512)
    const float* rel  = (const float*)d_in[1];   // (32, 256)
    const float* ent  = (const float*)d_in[2];   // (43234, 512)
    float* out = (float*)d_out;                  // (32, 43234)

    cudaFuncSetAttribute(dist_kernel, cudaFuncAttributeMaxDynamicSharedMemorySize, 65536);

    prep_kernel<<<32, 256>>>(head, rel);
    dist_kernel<<<NBLK, NTHR, 65536>>>(ent, out);
}